// round 2
// baseline (speedup 1.0000x reference)
#include <cuda_runtime.h>
#include <cstdint>

#define N_NODES 100000
#define N_EDGES 1600000
#define D 128
#define TILE_M 64

// Scratch for the projected features (allocation-free rule: __device__ global).
__device__ float g_support[(size_t)N_NODES * D];

// ---------------------------------------------------------------------------
// Kernel 1: out[row][c] = bias[c]  (output is poisoned 0xAA before timing)
// ---------------------------------------------------------------------------
__global__ void init_out_kernel(float* __restrict__ out, const float* __restrict__ bias)
{
    // operate in float4: 128 floats per row = 32 float4 per row
    size_t idx = (size_t)blockIdx.x * blockDim.x + threadIdx.x;
    size_t total = (size_t)N_NODES * (D / 4);
    const float4* b4 = (const float4*)bias;
    float4* o4 = (float4*)out;
    for (size_t i = idx; i < total; i += (size_t)gridDim.x * blockDim.x) {
        int c4 = (int)(i & 31);          // D/4 = 32 float4 per row
        o4[i] = __ldg(&b4[c4]);
    }
}

// ---------------------------------------------------------------------------
// Kernel 2: support = x @ W  (fp32, W and x-tile staged in smem)
// Block: 256 threads, computes TILE_M=64 rows x 128 cols.
// Thread (cg, rg): cols cg*4..cg*4+3, rows rg*8..rg*8+7 -> 32 accumulators.
// ---------------------------------------------------------------------------
__global__ void gemm_kernel(const float* __restrict__ x,
                            const float* __restrict__ W,
                            float* __restrict__ support,
                            int n_rows)
{
    extern __shared__ float smem[];
    float* Ws = smem;                 // [D][D]      64 KB
    float* xs = smem + D * D;         // [TILE_M][D] 32 KB

    int tid = threadIdx.x;
    int m0 = blockIdx.x * TILE_M;

    // Load W (128x128 = 4096 float4), 256 threads -> 16 each, coalesced.
    {
        const float4* Wg = (const float4*)W;
        float4* Wsh = (float4*)Ws;
        #pragma unroll
        for (int i = 0; i < (D * D / 4) / 256; i++) {
            int idx = tid + i * 256;
            Wsh[idx] = Wg[idx];
        }
    }
    // Load x tile (64 rows x 32 float4), 256 threads -> 8 each, coalesced.
    {
        const float4* xg = (const float4*)x;
        float4* xsh = (float4*)xs;
        #pragma unroll
        for (int i = 0; i < (TILE_M * (D / 4)) / 256; i++) {
            int idx = tid + i * 256;
            int r = idx >> 5;          // /32
            int c4 = idx & 31;
            int row = m0 + r;
            float4 v = make_float4(0.f, 0.f, 0.f, 0.f);
            if (row < n_rows) v = xg[(size_t)row * (D / 4) + c4];
            xsh[(size_t)r * (D / 4) + c4] = v;
        }
    }
    __syncthreads();

    int cg = tid & 31;    // column group -> cols cg*4 .. cg*4+3 (per-warp distinct -> LDS.128 conflict-free)
    int rg = tid >> 5;    // row group    -> rows rg*8 .. rg*8+7 (uniform within warp -> LDS broadcast)

    float acc[8][4];
    #pragma unroll
    for (int r = 0; r < 8; r++)
        #pragma unroll
        for (int c = 0; c < 4; c++) acc[r][c] = 0.f;

    const float* xrow = xs + (size_t)(rg * 8) * D;

    #pragma unroll 4
    for (int k = 0; k < D; k++) {
        float4 wv = *(const float4*)&Ws[(size_t)k * D + cg * 4];
        #pragma unroll
        for (int r = 0; r < 8; r++) {
            float xv = xrow[(size_t)r * D + k];
            acc[r][0] += xv * wv.x;
            acc[r][1] += xv * wv.y;
            acc[r][2] += xv * wv.z;
            acc[r][3] += xv * wv.w;
        }
    }

    #pragma unroll
    for (int r = 0; r < 8; r++) {
        int row = m0 + rg * 8 + r;
        if (row < n_rows) {
            float4 o = make_float4(acc[r][0], acc[r][1], acc[r][2], acc[r][3]);
            *(float4*)&support[(size_t)row * D + cg * 4] = o;
        }
    }
}

// ---------------------------------------------------------------------------
// Kernel 3: SpMM scatter. One warp per edge.
// Each lane handles 4 contiguous dims: gather float4 from support[src],
// scale by w, vectorized atomic reduce into out[dst].
// ---------------------------------------------------------------------------
__global__ void spmm_kernel(const float* __restrict__ support,
                            const int* __restrict__ esrc,
                            const int* __restrict__ edst,
                            const float* __restrict__ ew,
                            float* __restrict__ out)
{
    size_t gtid = (size_t)blockIdx.x * blockDim.x + threadIdx.x;
    size_t e = gtid >> 5;
    int lane = (int)(gtid & 31);
    if (e >= N_EDGES) return;

    int s = __ldg(&esrc[e]);
    int d = __ldg(&edst[e]);
    float w = __ldg(&ew[e]);

    float4 v = *(const float4*)&support[(size_t)s * D + lane * 4];
    float mx = v.x * w, my = v.y * w, mz = v.z * w, mw = v.w * w;

    float* p = &out[(size_t)d * D + lane * 4];
    asm volatile("red.global.add.v4.f32 [%0], {%1, %2, %3, %4};"
                 :: "l"(p), "f"(mx), "f"(my), "f"(mz), "f"(mw)
                 : "memory");
}

// ---------------------------------------------------------------------------
// Launch
// Inputs (metadata order): x [N,128] f32, edge_src [E] i32, edge_dst [E] i32,
//                          edge_weight [E] f32, W [128,128] f32, bias [128] f32
// Output: [N,128] f32
// ---------------------------------------------------------------------------
extern "C" void kernel_launch(void* const* d_in, const int* in_sizes, int n_in,
                              void* d_out, int out_size)
{
    const float* x    = (const float*)d_in[0];
    const int*   esrc = (const int*)d_in[1];
    const int*   edst = (const int*)d_in[2];
    const float* ew   = (const float*)d_in[3];
    const float* W    = (const float*)d_in[4];
    const float* bias = (const float*)d_in[5];
    float* out = (float*)d_out;

    float* support;
    cudaGetSymbolAddress((void**)&support, g_support);

    // init out = bias
    {
        int threads = 256;
        int blocks = 2048;
        init_out_kernel<<<blocks, threads>>>(out, bias);
    }

    // support = x @ W
    {
        static const int smem_bytes = (D * D + TILE_M * D) * (int)sizeof(float); // 96 KB
        cudaFuncSetAttribute(gemm_kernel, cudaFuncAttributeMaxDynamicSharedMemorySize, smem_bytes);
        int blocks = (N_NODES + TILE_M - 1) / TILE_M;
        gemm_kernel<<<blocks, 256, smem_bytes>>>(x, W, support, N_NODES);
    }

    // scatter
    {
        int threads = 256;                       // 8 warps -> 8 edges per block
        size_t total_threads = (size_t)N_EDGES * 32;
        int blocks = (int)((total_threads + threads - 1) / threads);
        spmm_kernel<<<blocks, threads>>>(support, esrc, edst, ew, out);
    }
}

// round 3
// speedup vs baseline: 1.5097x; 1.5097x over previous
#include <cuda_runtime.h>
#include <cstdint>

#define N_NODES 100000
#define N_EDGES 1600000
#define D 128
#define TILE_M 64
#define SCAN_BLOCK 512
#define NB_SCAN ((N_NODES + SCAN_BLOCK - 1) / SCAN_BLOCK)   // 196

// ---- device scratch (allocation-free rule: __device__ globals) ----
__device__ float g_support[(size_t)N_NODES * D];   // x @ W
__device__ int   g_count[N_NODES];                 // histogram of dst
__device__ int   g_offset[N_NODES + 1];            // CSR row offsets
__device__ int   g_cursor[N_NODES];                // scatter cursors
__device__ int   g_blocksum[NB_SCAN];              // scan partials
__device__ uint2 g_edges[N_EDGES];                 // {src, float_bits(w)} sorted by dst

static_assert(NB_SCAN <= 256, "scan2 single block assumption");

// ---------------------------------------------------------------------------
// CSR build step 1: histogram of edge_dst
// ---------------------------------------------------------------------------
__global__ void hist_kernel(const int* __restrict__ edst)
{
    int i = blockIdx.x * blockDim.x + threadIdx.x;
    int stride = gridDim.x * blockDim.x;
    for (; i < N_EDGES; i += stride)
        atomicAdd(&g_count[edst[i]], 1);           // no return use -> REDG
}

// ---------------------------------------------------------------------------
// CSR build step 2a: per-block exclusive scan of g_count -> g_offset (local),
// block totals -> g_blocksum
// ---------------------------------------------------------------------------
__global__ void scan1_kernel()
{
    __shared__ int warp_sums[SCAN_BLOCK / 32];
    int tid = threadIdx.x;
    int gid = blockIdx.x * SCAN_BLOCK + tid;
    int v = (gid < N_NODES) ? g_count[gid] : 0;

    // inclusive warp scan
    int x = v;
    #pragma unroll
    for (int o = 1; o < 32; o <<= 1) {
        int y = __shfl_up_sync(0xFFFFFFFFu, x, o);
        if ((tid & 31) >= o) x += y;
    }
    if ((tid & 31) == 31) warp_sums[tid >> 5] = x;
    __syncthreads();
    if (tid < 32) {
        const int nw = SCAN_BLOCK / 32;            // 16
        int s = (tid < nw) ? warp_sums[tid] : 0;
        #pragma unroll
        for (int o = 1; o < 32; o <<= 1) {
            int y = __shfl_up_sync(0xFFFFFFFFu, s, o);
            if (tid >= o) s += y;
        }
        if (tid < nw) warp_sums[tid] = s;          // inclusive warp totals
    }
    __syncthreads();
    int base = (tid >= 32) ? warp_sums[(tid >> 5) - 1] : 0;
    int incl = x + base;
    if (gid < N_NODES) g_offset[gid] = incl - v;   // block-local exclusive
    if (tid == SCAN_BLOCK - 1) g_blocksum[blockIdx.x] = incl;
}

// ---------------------------------------------------------------------------
// CSR build step 2b: exclusive scan of the 196 block totals (1 block)
// ---------------------------------------------------------------------------
__global__ void scan2_kernel()
{
    __shared__ int sh[256];
    int tid = threadIdx.x;
    int v = (tid < NB_SCAN) ? g_blocksum[tid] : 0;
    sh[tid] = v;
    __syncthreads();
    #pragma unroll
    for (int o = 1; o < 256; o <<= 1) {
        int y = (tid >= o) ? sh[tid - o] : 0;
        __syncthreads();
        sh[tid] += y;
        __syncthreads();
    }
    if (tid < NB_SCAN) g_blocksum[tid] = sh[tid] - v;   // exclusive
}

// ---------------------------------------------------------------------------
// CSR build step 2c: add block bases, init cursors, cap offsets
// ---------------------------------------------------------------------------
__global__ void scan3_kernel()
{
    int gid = blockIdx.x * SCAN_BLOCK + threadIdx.x;
    if (gid < N_NODES) {
        int o = g_offset[gid] + g_blocksum[blockIdx.x];
        g_offset[gid] = o;
        g_cursor[gid] = o;
    }
    if (gid == 0) g_offset[N_NODES] = N_EDGES;
}

// ---------------------------------------------------------------------------
// CSR build step 3: scatter edges into dst-sorted order
// ---------------------------------------------------------------------------
__global__ void scatter_kernel(const int* __restrict__ esrc,
                               const int* __restrict__ edst,
                               const float* __restrict__ ew)
{
    int i = blockIdx.x * blockDim.x + threadIdx.x;
    int stride = gridDim.x * blockDim.x;
    for (; i < N_EDGES; i += stride) {
        int d = edst[i];
        int pos = atomicAdd(&g_cursor[d], 1);
        g_edges[pos] = make_uint2((unsigned)esrc[i], __float_as_uint(ew[i]));
    }
}

// ---------------------------------------------------------------------------
// GEMM: support = x @ W  (fp32, smem-staged, 64x128 tile per 256-thread block)
// ---------------------------------------------------------------------------
__global__ void gemm_kernel(const float* __restrict__ x,
                            const float* __restrict__ W,
                            float* __restrict__ support,
                            int n_rows)
{
    extern __shared__ float smem[];
    float* Ws = smem;                 // [D][D]      64 KB
    float* xs = smem + D * D;         // [TILE_M][D] 32 KB

    int tid = threadIdx.x;
    int m0 = blockIdx.x * TILE_M;

    {
        const float4* Wg = (const float4*)W;
        float4* Wsh = (float4*)Ws;
        #pragma unroll
        for (int i = 0; i < (D * D / 4) / 256; i++)
            Wsh[tid + i * 256] = Wg[tid + i * 256];
    }
    {
        const float4* xg = (const float4*)x;
        float4* xsh = (float4*)xs;
        #pragma unroll
        for (int i = 0; i < (TILE_M * (D / 4)) / 256; i++) {
            int idx = tid + i * 256;
            int r = idx >> 5;
            int c4 = idx & 31;
            int row = m0 + r;
            float4 v = make_float4(0.f, 0.f, 0.f, 0.f);
            if (row < n_rows) v = xg[(size_t)row * (D / 4) + c4];
            xsh[(size_t)r * (D / 4) + c4] = v;
        }
    }
    __syncthreads();

    int cg = tid & 31;
    int rg = tid >> 5;

    float acc[8][4];
    #pragma unroll
    for (int r = 0; r < 8; r++)
        #pragma unroll
        for (int c = 0; c < 4; c++) acc[r][c] = 0.f;

    const float* xrow = xs + (size_t)(rg * 8) * D;

    #pragma unroll 4
    for (int k = 0; k < D; k++) {
        float4 wv = *(const float4*)&Ws[(size_t)k * D + cg * 4];
        #pragma unroll
        for (int r = 0; r < 8; r++) {
            float xv = xrow[(size_t)r * D + k];
            acc[r][0] += xv * wv.x;
            acc[r][1] += xv * wv.y;
            acc[r][2] += xv * wv.z;
            acc[r][3] += xv * wv.w;
        }
    }

    #pragma unroll
    for (int r = 0; r < 8; r++) {
        int row = m0 + rg * 8 + r;
        if (row < n_rows)
            *(float4*)&support[(size_t)row * D + cg * 4] =
                make_float4(acc[r][0], acc[r][1], acc[r][2], acc[r][3]);
    }
}

// ---------------------------------------------------------------------------
// Gather SpMM: one warp per dst node. Register accumulation, one write.
// out[d] = bias + sum_{e in CSR[d]} w_e * support[src_e]
// ---------------------------------------------------------------------------
__global__ void gather_kernel(const float* __restrict__ bias,
                              float* __restrict__ out)
{
    int warp = (blockIdx.x * blockDim.x + threadIdx.x) >> 5;
    int lane = threadIdx.x & 31;
    if (warp >= N_NODES) return;

    int start = g_offset[warp];
    int end   = g_offset[warp + 1];

    const float4* sup4 = (const float4*)g_support;
    float4 acc = __ldg(&((const float4*)bias)[lane]);

    for (int i = start; i < end; i += 32) {
        int n = end - i;
        if (n > 32) n = 32;
        uint2 em = make_uint2(0u, 0u);
        if (lane < n) em = g_edges[i + lane];
        for (int j = 0; j < n; j++) {
            unsigned s = __shfl_sync(0xFFFFFFFFu, em.x, j);
            float    w = __uint_as_float(__shfl_sync(0xFFFFFFFFu, em.y, j));
            float4 v = sup4[(size_t)s * (D / 4) + lane];
            acc.x += w * v.x;
            acc.y += w * v.y;
            acc.z += w * v.z;
            acc.w += w * v.w;
        }
    }
    ((float4*)out)[(size_t)warp * (D / 4) + lane] = acc;
}

// ---------------------------------------------------------------------------
// Launch.  Inputs: x, edge_src, edge_dst, edge_weight, W, bias. Output fp32.
// ---------------------------------------------------------------------------
extern "C" void kernel_launch(void* const* d_in, const int* in_sizes, int n_in,
                              void* d_out, int out_size)
{
    const float* x    = (const float*)d_in[0];
    const int*   esrc = (const int*)d_in[1];
    const int*   edst = (const int*)d_in[2];
    const float* ew   = (const float*)d_in[3];
    const float* W    = (const float*)d_in[4];
    const float* bias = (const float*)d_in[5];
    float* out = (float*)d_out;

    float* support;
    cudaGetSymbolAddress((void**)&support, g_support);
    void* countPtr;
    cudaGetSymbolAddress(&countPtr, g_count);

    // --- CSR build ---
    cudaMemsetAsync(countPtr, 0, N_NODES * sizeof(int));
    hist_kernel<<<1024, 256>>>(edst);
    scan1_kernel<<<NB_SCAN, SCAN_BLOCK>>>();
    scan2_kernel<<<1, 256>>>();
    scan3_kernel<<<NB_SCAN, SCAN_BLOCK>>>();
    scatter_kernel<<<1024, 256>>>(esrc, edst, ew);

    // --- dense projection ---
    {
        static const int smem_bytes = (D * D + TILE_M * D) * (int)sizeof(float); // 96 KB
        cudaFuncSetAttribute(gemm_kernel, cudaFuncAttributeMaxDynamicSharedMemorySize, smem_bytes);
        int blocks = (N_NODES + TILE_M - 1) / TILE_M;
        gemm_kernel<<<blocks, 256, smem_bytes>>>(x, W, support, N_NODES);
    }

    // --- gather SpMM + bias ---
    {
        int warps_per_block = 8;                    // 256 threads
        int blocks = (N_NODES + warps_per_block - 1) / warps_per_block;
        gather_kernel<<<blocks, 256>>>(bias, out);
    }
}